// round 1
// baseline (speedup 1.0000x reference)
#include <cuda_runtime.h>
#include <cstdint>

#define NTASKS 64
#define NROWS  2048
#define INSZ   512
#define OUTSZ  512

// Scratch (device globals: no allocation allowed in kernel_launch)
__device__ int g_row_order[NROWS];
__device__ int g_task_off[NTASKS + 1];

// ---------------------------------------------------------------------------
// Kernel 1: counting sort of rows by task id. Single block, 256 threads.
// Robust to task_ids being int64 (reference declares int64) or int32 (JAX
// without x64 silently downcasts): for int64 little-endian values < 2^31 the
// odd 32-bit words are all zero; for real int32 data the odd words are random
// task ids in [0,64) — P(all zero) ~ 64^-1024.
// ---------------------------------------------------------------------------
__global__ void sort_rows_kernel(const void* __restrict__ task_ids_raw) {
    __shared__ int counts[NTASKS];
    __shared__ int offs[NTASKS + 1];
    __shared__ int cursor[NTASKS];
    __shared__ int is64;

    const int tid = threadIdx.x;
    if (tid < NTASKS) counts[tid] = 0;
    if (tid == 0) is64 = 1;
    __syncthreads();

    const int* as32 = (const int*)task_ids_raw;
    // Only inspect first 2048 32-bit words (in-bounds for both widths).
    int nz = 0;
    for (int i = tid; i < NROWS / 2; i += blockDim.x)
        if (as32[2 * i + 1] != 0) nz = 1;
    if (nz) atomicExch(&is64, 0);
    __syncthreads();
    const int wide = is64;

    for (int i = tid; i < NROWS; i += blockDim.x) {
        int t = wide ? as32[2 * i] : as32[i];
        atomicAdd(&counts[t], 1);
    }
    __syncthreads();

    if (tid == 0) {
        int s = 0;
        for (int t = 0; t < NTASKS; t++) { offs[t] = s; cursor[t] = s; s += counts[t]; }
        offs[NTASKS] = s;
    }
    __syncthreads();

    if (tid <= NTASKS) g_task_off[tid] = offs[tid];

    for (int i = tid; i < NROWS; i += blockDim.x) {
        int t = wide ? as32[2 * i] : as32[i];
        int p = atomicAdd(&cursor[t], 1);
        g_row_order[p] = i;
    }
}

// ---------------------------------------------------------------------------
// Kernel 2: per-task GEMM. grid = (OUT/128 = 4, NTASKS = 64), 256 threads.
// Block tile: up to 32 rows x 128 cols, K-tile = 64 through SMEM.
// Thread tile: 4 rows x 4 cols, accumulated as packed f32x2 pairs via
// fma.rn.f32x2 (2 FMAs per issued instruction on the fma pipe).
// Each W element is read from HBM exactly once across the whole grid.
// ---------------------------------------------------------------------------
__global__ __launch_bounds__(256, 2)
void task_gemm_kernel(const float* __restrict__ X,
                      const float* __restrict__ W,
                      float* __restrict__ Out) {
    __shared__ __align__(16) float Xs[32][64];
    __shared__ __align__(16) float Ws[64][128];

    const int t    = blockIdx.y;
    const int col0 = blockIdx.x * 128;
    const int r0   = g_task_off[t];
    const int r1   = g_task_off[t + 1];
    if (r0 >= r1) return;

    const int tid = threadIdx.x;
    const int tc  = tid & 31;   // column group: cols col0 + tc*4 .. +3
    const int tr  = tid >> 5;   // row group: rows tr*4 .. +3

    const float* __restrict__ Wt = W + (size_t)t * INSZ * OUTSZ;

    for (int rowbase = r0; rowbase < r1; rowbase += 32) {
        const int nrows = min(32, r1 - rowbase);

        unsigned long long acc[4][2];
        #pragma unroll
        for (int r = 0; r < 4; r++) { acc[r][0] = 0ull; acc[r][1] = 0ull; }

        for (int kt = 0; kt < INSZ; kt += 64) {
            // --- load X tile: 32 rows x 64 cols (2048 floats, 8 per thread) ---
            {
                const int lr = tid >> 3;            // 0..31
                const int lc = (tid & 7) * 8;       // 0,8,...,56
                float4 v0, v1;
                if (lr < nrows) {
                    const int grow = g_row_order[rowbase + lr];
                    const float4* src =
                        (const float4*)(X + (size_t)grow * INSZ + kt + lc);
                    v0 = src[0]; v1 = src[1];
                } else {
                    v0 = make_float4(0.f, 0.f, 0.f, 0.f); v1 = v0;
                }
                *(float4*)&Xs[lr][lc]     = v0;
                *(float4*)&Xs[lr][lc + 4] = v1;
            }
            // --- load W tile: 64 x 128 floats (8192 floats, 8 float4/thread) ---
            #pragma unroll
            for (int p = 0; p < 8; p++) {
                const int f4   = tid + p * 256;
                const int wrow = f4 >> 5;
                const int wcol = (f4 & 31) << 2;
                *(float4*)&Ws[wrow][wcol] =
                    *(const float4*)(Wt + (size_t)(kt + wrow) * OUTSZ + col0 + wcol);
            }
            __syncthreads();

            #pragma unroll 8
            for (int i = 0; i < 64; i++) {
                // two packed f32x2 weight pairs for this thread's 4 columns
                const ulonglong2 w2 = *(const ulonglong2*)&Ws[i][tc * 4];
                #pragma unroll
                for (int r = 0; r < 4; r++) {
                    const unsigned int xb = __float_as_uint(Xs[tr * 4 + r][i]);
                    unsigned long long xx;
                    asm("mov.b64 %0, {%1, %1};" : "=l"(xx) : "r"(xb));
                    asm("fma.rn.f32x2 %0, %1, %2, %0;"
                        : "+l"(acc[r][0]) : "l"(xx), "l"(w2.x));
                    asm("fma.rn.f32x2 %0, %1, %2, %0;"
                        : "+l"(acc[r][1]) : "l"(xx), "l"(w2.y));
                }
            }
            __syncthreads();
        }

        // --- store: each thread owns 4 rows x 4 cols ---
        #pragma unroll
        for (int r = 0; r < 4; r++) {
            const int lr = tr * 4 + r;
            if (lr < nrows) {
                const int grow = g_row_order[rowbase + lr];
                unsigned int a0, a1, a2, a3;
                asm("mov.b64 {%0, %1}, %2;" : "=r"(a0), "=r"(a1) : "l"(acc[r][0]));
                asm("mov.b64 {%0, %1}, %2;" : "=r"(a2), "=r"(a3) : "l"(acc[r][1]));
                float4 o;
                o.x = __uint_as_float(a0);
                o.y = __uint_as_float(a1);
                o.z = __uint_as_float(a2);
                o.w = __uint_as_float(a3);
                *(float4*)(Out + (size_t)grow * OUTSZ + col0 + tc * 4) = o;
            }
        }
    }
}

extern "C" void kernel_launch(void* const* d_in, const int* in_sizes, int n_in,
                              void* d_out, int out_size) {
    const float* X        = (const float*)d_in[0];   // [2048, 512] fp32
    const void*  task_ids = d_in[1];                 // [2048] int64 (or int32)
    const float* W        = (const float*)d_in[2];   // [64, 512, 512] fp32
    float*       Out      = (float*)d_out;           // [2048, 512] fp32

    sort_rows_kernel<<<1, 256>>>(task_ids);
    dim3 grid(OUTSZ / 128, NTASKS);
    task_gemm_kernel<<<grid, 256>>>(X, W, Out);
}